// round 14
// baseline (speedup 1.0000x reference)
#include <cuda_runtime.h>
#include <cstdint>

#define NN 50000
#define EE 500000
#define HH 128
#define SCAN_NB 196   // ceil(50000/256)
#define NB0 391       // ceil(50000/128)  blocks for scalar-channel GEMM
#define NB1 1172      // ceil(150000/128) blocks for vector-channel GEMM

// ---- scratch (static __device__ arrays; no runtime allocation) ----
__device__ int      g_cnt[NN];
__device__ int      g_off[NN + 1];
__device__ int      g_cur[NN];
__device__ int      g_cols[EE];
__device__ int      g_blksum[SCAN_NB];
__device__ int      g_is32;
__device__ float    g_agg[(size_t)NN * 512];
// pre-split weights, bf16 hi/lo: [0]=s_root [1]=s_rel [2]=v_root [3]=v_rel
__device__ uint16_t g_whi[4][16384];
__device__ uint16_t g_wlo[4][16384];

// ================= warp-mma helpers (sm_80+ PTX, valid for compute_103) =========
__device__ __forceinline__ uint32_t smem_u32(const void* p) {
    uint32_t a;
    asm("{ .reg .u64 t; cvta.to.shared.u64 t, %1; cvt.u32.u64 %0, t; }" : "=r"(a) : "l"(p));
    return a;
}
__device__ __forceinline__ void ldsm_x4(uint32_t* r, uint32_t addr) {
    asm volatile("ldmatrix.sync.aligned.m8n8.x4.shared.b16 {%0,%1,%2,%3}, [%4];"
                 : "=r"(r[0]), "=r"(r[1]), "=r"(r[2]), "=r"(r[3]) : "r"(addr));
}
__device__ __forceinline__ void ldsm_x2(uint32_t* r, uint32_t addr) {
    asm volatile("ldmatrix.sync.aligned.m8n8.x2.shared.b16 {%0,%1}, [%2];"
                 : "=r"(r[0]), "=r"(r[1]) : "r"(addr));
}
__device__ __forceinline__ void mma_bf16(float* c, const uint32_t* a, const uint32_t* b) {
    asm volatile("mma.sync.aligned.m16n8k16.row.col.f32.bf16.bf16.f32 "
                 "{%0,%1,%2,%3}, {%4,%5,%6,%7}, {%8,%9}, {%0,%1,%2,%3};"
                 : "+f"(c[0]), "+f"(c[1]), "+f"(c[2]), "+f"(c[3])
                 : "r"(a[0]), "r"(a[1]), "r"(a[2]), "r"(a[3]), "r"(b[0]), "r"(b[1]));
}
__device__ __forceinline__ uint32_t pack_bf16x2(float hi_el, float lo_el) {
    uint32_t r;
    asm("cvt.rn.bf16x2.f32 %0, %1, %2;" : "=r"(r) : "f"(hi_el), "f"(lo_el));
    return r;
}

// ---------------- dtype detection + zero (fused) ----------------
__global__ void k_init() {
    int i = blockIdx.x * blockDim.x + threadIdx.x;
    if (i == 0) g_is32 = 0;
    if (i < NN) g_cnt[i] = 0;
}

__global__ void k_dtype_detect(const long long* __restrict__ ei) {
    int e = blockIdx.x * blockDim.x + threadIdx.x;
    if (e < EE) {
        long long v = ei[e];
        if (v < 0 || v >= NN) atomicOr(&g_is32, 1);
    }
}

__device__ __forceinline__ int load_idx(const void* ei, int pos, int is32) {
    long long v;
    if (is32) v = ((const int*)ei)[pos];
    else      v = ((const long long*)ei)[pos];
    int r = (int)v;
    if (r < 0) r = 0;
    if (r >= NN) r = NN - 1;
    return r;
}

// ---------------- weight pre-split: fp32 -> bf16 hi + bf16 lo ----------------
__global__ void __launch_bounds__(256) k_wsplit(const float* __restrict__ a,
                                                const float* __restrict__ b,
                                                const float* __restrict__ c,
                                                const float* __restrict__ d) {
    int i = blockIdx.x * 256 + threadIdx.x;      // 0..65535
    int mat = i >> 14;
    int idx = i & 16383;
    const float* src = (mat == 0) ? a : (mat == 1) ? b : (mat == 2) ? c : d;
    float f = src[idx];
    uint32_t u = __float_as_uint(f);
    g_whi[mat][idx] = (uint16_t)(u >> 16);                       // truncation
    float lo = f - __uint_as_float(u & 0xFFFF0000u);             // exact residual
    g_wlo[mat][idx] = (uint16_t)(pack_bf16x2(0.f, lo) & 0xFFFFu);
}

// ---------------- CSR build ----------------
__global__ void k_hist(const void* __restrict__ ei) {
    int e = blockIdx.x * blockDim.x + threadIdx.x;
    if (e < EE) {
        int is32 = g_is32;
        int r = load_idx(ei, e, is32);
        atomicAdd(&g_cnt[r], 1);
    }
}

__global__ void __launch_bounds__(256) k_scan1() {
    __shared__ int s[256];
    int t = threadIdx.x;
    int i = blockIdx.x * 256 + t;
    int v = (i < NN) ? g_cnt[i] : 0;
    s[t] = v;
    __syncthreads();
#pragma unroll
    for (int d = 1; d < 256; d <<= 1) {
        int u = (t >= d) ? s[t - d] : 0;
        __syncthreads();
        s[t] += u;
        __syncthreads();
    }
    if (i < NN) g_off[i] = s[t] - v;
    if (t == 255) g_blksum[blockIdx.x] = s[255];
}

__global__ void __launch_bounds__(256) k_scan2() {
    __shared__ int s[256];
    int t = threadIdx.x;
    int v = (t < SCAN_NB) ? g_blksum[t] : 0;
    s[t] = v;
    __syncthreads();
#pragma unroll
    for (int d = 1; d < 256; d <<= 1) {
        int u = (t >= d) ? s[t - d] : 0;
        __syncthreads();
        s[t] += u;
        __syncthreads();
    }
    if (t < SCAN_NB) g_blksum[t] = s[t] - v;
}

__global__ void __launch_bounds__(256) k_scan3() {
    int t = threadIdx.x;
    int i = blockIdx.x * 256 + t;
    if (i < NN) {
        int o = g_off[i] + g_blksum[blockIdx.x];
        g_off[i] = o;
        g_cur[i] = o;
    }
    if (i == NN) g_off[NN] = EE;
}

__global__ void k_fill(const void* __restrict__ ei) {
    int e = blockIdx.x * blockDim.x + threadIdx.x;
    if (e < EE) {
        int is32 = g_is32;
        int r = load_idx(ei, e, is32);
        int c = load_idx(ei, EE + e, is32);
        int p = atomicAdd(&g_cur[r], 1);
        g_cols[p] = c;
    }
}

// ---------------- aggregate raw features: agg[n] = sum_{e: row=n} x[col_e] ----------------
__global__ void __launch_bounds__(128) k_agg(const float4* __restrict__ xv) {
    int n = blockIdx.x;
    int t = threadIdx.x;
    int beg = g_off[n], end = g_off[n + 1];
    float4 acc = make_float4(0.f, 0.f, 0.f, 0.f);
    int j = beg;
    for (; j + 3 < end; j += 4) {
        int c0 = g_cols[j], c1 = g_cols[j + 1], c2 = g_cols[j + 2], c3 = g_cols[j + 3];
        float4 v0 = xv[(size_t)c0 * 128 + t];
        float4 v1 = xv[(size_t)c1 * 128 + t];
        float4 v2 = xv[(size_t)c2 * 128 + t];
        float4 v3 = xv[(size_t)c3 * 128 + t];
        acc.x += v0.x + v1.x + v2.x + v3.x;
        acc.y += v0.y + v1.y + v2.y + v3.y;
        acc.z += v0.z + v1.z + v2.z + v3.z;
        acc.w += v0.w + v1.w + v2.w + v3.w;
    }
    for (; j < end; j++) {
        int c0 = g_cols[j];
        float4 v0 = xv[(size_t)c0 * 128 + t];
        acc.x += v0.x; acc.y += v0.y; acc.z += v0.z; acc.w += v0.w;
    }
    ((float4*)g_agg)[(size_t)n * 128 + t] = acc;
}

// ---------------- fused 3xBF16 mma.sync GEMM (both channels, one launch) ----------------
// block < NB0: scalar rows (mode 0, +bias). block >= NB0: vector rows (mode 1).
// 128x128 tile, K=256 in 8 chunks of 32. Double-buffered smem, 1 sync/chunk.
// A: fp32 LDG (prefetched) -> reg split -> bf16 hi/lo STS.
// B: pre-split bf16 LDG -> STS (no conversion).

#define TSTRIDE 80                       // bytes per 32-bf16 row (64 + 16 pad)
#define TILE_B  10240                    // 128 * TSTRIDE
#define BUF_B   (4 * TILE_B)             // AHI, ALO, BHI, BLO
#define SMEM_MG (512 + 2 * BUF_B)        // roff + 2 buffers = 82432 bytes

__global__ void __launch_bounds__(256) k_mgemm(const float* __restrict__ X,
                                               const float* __restrict__ bias,
                                               float* __restrict__ out) {
    extern __shared__ __align__(16) char sm[];
    int* roff_s = (int*)sm;
    uint32_t sbase = smem_u32(sm);

    int tid = threadIdx.x;
    int lane = tid & 31;
    int wid = tid >> 5;

    int mode, mb, Mloc;
    if (blockIdx.x < NB0) { mode = 0; mb = (int)blockIdx.x;       Mloc = NN; }
    else                  { mode = 1; mb = (int)blockIdx.x - NB0; Mloc = 3 * NN; }
    int mbase = mb * 128;

    if (tid < 128) {
        int m = mbase + tid;
        if (m >= Mloc) m = Mloc - 1;     // clamp: duplicate loads, stores guarded
        int off;
        if (mode == 0) off = m * 512;
        else { int n = m / 3; int ch = 1 + (m % 3); off = n * 512 + ch * 128; }
        roff_s[tid] = off;
    }
    __syncthreads();

    // load roles
    int lrow = tid >> 1;                 // 0..127
    int khf  = (tid & 1) * 16;           // float offset within 32-wide chunk
    int arow = roff_s[lrow];
    uint32_t st_off = (uint32_t)lrow * TSTRIDE + (uint32_t)khf * 2;

    const uint16_t* WH0 = g_whi[mode * 2 + 0];  // root
    const uint16_t* WH1 = g_whi[mode * 2 + 1];  // rel
    const uint16_t* WL0 = g_wlo[mode * 2 + 0];
    const uint16_t* WL1 = g_wlo[mode * 2 + 1];

    // compute roles
    int warpM = wid & 3;
    int warpN = wid >> 2;
    int g  = lane >> 3;
    int rr = lane & 7;
    uint32_t aoff0 = (uint32_t)(warpM * 32 + rr + (g & 1) * 8) * TSTRIDE + (g >> 1) * 16;
    uint32_t aoff1 = aoff0 + 16 * TSTRIDE;
    uint32_t boff  = (uint32_t)(warpN * 64 + rr) * TSTRIDE + ((lane >> 3) & 1) * 16;

    float acc[2][8][4];
#pragma unroll
    for (int mt = 0; mt < 2; mt++)
#pragma unroll
        for (int nt = 0; nt < 8; nt++)
#pragma unroll
            for (int q = 0; q < 4; q++) acc[mt][nt][q] = 0.f;

    const float* Agg = g_agg;
    float4 af[4];   // A prefetch registers

    auto LDA = [&](int c) {
        bool fh = (c < 4);
        int koff = (c & 3) * 32;
        const float* pa = (fh ? X : Agg) + arow + koff + khf;
#pragma unroll
        for (int q = 0; q < 4; q++) af[q] = ((const float4*)pa)[q];
    };
    auto STA = [&](int buf) {
        char* p = sm + 512 + buf * BUF_B;
#pragma unroll
        for (int q = 0; q < 4; q++) {
            float4 f = af[q];
            uint32_t ux = __float_as_uint(f.x), uy = __float_as_uint(f.y);
            uint32_t uz = __float_as_uint(f.z), uw = __float_as_uint(f.w);
            uint2 h, l;
            h.x = __byte_perm(ux, uy, 0x7632);
            h.y = __byte_perm(uz, uw, 0x7632);
            float lx = f.x - __uint_as_float(ux & 0xFFFF0000u);
            float ly = f.y - __uint_as_float(uy & 0xFFFF0000u);
            float lz = f.z - __uint_as_float(uz & 0xFFFF0000u);
            float lw = f.w - __uint_as_float(uw & 0xFFFF0000u);
            l.x = pack_bf16x2(ly, lx);
            l.y = pack_bf16x2(lw, lz);
            *(uint2*)(p + st_off + q * 8) = h;               // AHI
            *(uint2*)(p + TILE_B + st_off + q * 8) = l;      // ALO
        }
    };
    auto LDSTB = [&](int c, int buf) {
        bool fh = (c < 4);
        int koff = (c & 3) * 32;
        const uint16_t* bh = (fh ? WH0 : WH1) + lrow * 128 + koff + khf;
        const uint16_t* bl = (fh ? WL0 : WL1) + lrow * 128 + koff + khf;
        uint4 h0 = ((const uint4*)bh)[0], h1 = ((const uint4*)bh)[1];
        uint4 l0 = ((const uint4*)bl)[0], l1 = ((const uint4*)bl)[1];
        char* p = sm + 512 + buf * BUF_B;
        *(uint4*)(p + 2 * TILE_B + st_off)      = h0;        // BHI
        *(uint4*)(p + 2 * TILE_B + st_off + 16) = h1;
        *(uint4*)(p + 3 * TILE_B + st_off)      = l0;        // BLO
        *(uint4*)(p + 3 * TILE_B + st_off + 16) = l1;
    };

    // prologue: fill buffer 0
    LDA(0);
    STA(0);
    LDSTB(0, 0);
    __syncthreads();

#pragma unroll 1
    for (int c = 0; c < 8; c++) {
        int cur = c & 1;
        if (c < 7) LDA(c + 1);           // A prefetch overlaps MMA below

        uint32_t bb = sbase + 512 + (uint32_t)cur * BUF_B;
#pragma unroll
        for (int ks = 0; ks < 2; ks++) {
            uint32_t a0h[4], a0l[4], a1h[4], a1l[4];
            ldsm_x4(a0h, bb + aoff0 + ks * 32);
            ldsm_x4(a0l, bb + TILE_B + aoff0 + ks * 32);
            ldsm_x4(a1h, bb + aoff1 + ks * 32);
            ldsm_x4(a1l, bb + TILE_B + aoff1 + ks * 32);
#pragma unroll
            for (int nt = 0; nt < 8; nt++) {
                uint32_t bh[2], bl[2];
                ldsm_x2(bh, bb + 2 * TILE_B + boff + nt * (8 * TSTRIDE) + ks * 32);
                ldsm_x2(bl, bb + 3 * TILE_B + boff + nt * (8 * TSTRIDE) + ks * 32);
                mma_bf16(acc[0][nt], a0h, bh);
                mma_bf16(acc[0][nt], a0l, bh);
                mma_bf16(acc[0][nt], a0h, bl);
                mma_bf16(acc[1][nt], a1h, bh);
                mma_bf16(acc[1][nt], a1l, bh);
                mma_bf16(acc[1][nt], a1h, bl);
            }
        }

        if (c < 7) {
            STA(cur ^ 1);
            LDSTB(c + 1, cur ^ 1);
            __syncthreads();
        }
    }

    // epilogue
#pragma unroll
    for (int mt = 0; mt < 2; mt++) {
        int lr0 = warpM * 32 + mt * 16 + (lane >> 2);
        int lr1 = lr0 + 8;
        bool live0 = (mbase + lr0) < Mloc;
        bool live1 = (mbase + lr1) < Mloc;
        int o0 = roff_s[lr0];
        int o1 = roff_s[lr1];
#pragma unroll
        for (int nt = 0; nt < 8; nt++) {
            int col = warpN * 64 + nt * 8 + 2 * (lane & 3);
            float b0 = 0.f, b1 = 0.f;
            if (mode == 0) { b0 = bias[col]; b1 = bias[col + 1]; }
            if (live0) {
                float2 v = make_float2(acc[mt][nt][0] + b0, acc[mt][nt][1] + b1);
                *(float2*)(out + o0 + col) = v;
            }
            if (live1) {
                float2 v = make_float2(acc[mt][nt][2] + b0, acc[mt][nt][3] + b1);
                *(float2*)(out + o1 + col) = v;
            }
        }
    }
}

extern "C" void kernel_launch(void* const* d_in, const int* in_sizes, int n_in,
                              void* d_out, int out_size) {
    const float* x        = (const float*)d_in[0];
    const void*  ei       = d_in[1];
    const float* W_s_rel  = (const float*)d_in[2];
    const float* W_s_root = (const float*)d_in[3];
    const float* b_s_root = (const float*)d_in[4];
    const float* W_v_rel  = (const float*)d_in[5];
    const float* W_v_root = (const float*)d_in[6];
    float*       out      = (float*)d_out;

    k_init<<<(NN + 255) / 256, 256>>>();
    k_dtype_detect<<<(EE + 255) / 256, 256>>>((const long long*)ei);
    k_wsplit<<<256, 256>>>(W_s_root, W_s_rel, W_v_root, W_v_rel);
    k_hist<<<(EE + 255) / 256, 256>>>(ei);
    k_scan1<<<SCAN_NB, 256>>>();
    k_scan2<<<1, 256>>>();
    k_scan3<<<SCAN_NB + 1, 256>>>();
    k_fill<<<(EE + 255) / 256, 256>>>(ei);
    k_agg<<<NN, 128>>>((const float4*)x);

    cudaFuncSetAttribute(k_mgemm, cudaFuncAttributeMaxDynamicSharedMemorySize, SMEM_MG);
    k_mgemm<<<NB0 + NB1, 256, SMEM_MG>>>(x, b_s_root, out);
}

// round 15
// speedup vs baseline: 1.1118x; 1.1118x over previous
#include <cuda_runtime.h>
#include <cstdint>

#define NN 50000
#define EE 500000
#define HH 128
#define SCAN_NB 196   // ceil(50000/256)
#define NB0 391       // ceil(50000/128)  blocks for scalar-channel tiles
#define NB1 1172      // ceil(150000/128) blocks for vector-channel tiles

// ---- scratch (static __device__ arrays; no runtime allocation) ----
__device__ int      g_cnt[NN];
__device__ int      g_off[NN + 1];
__device__ int      g_cur[NN];
__device__ int      g_cols[EE];
__device__ int      g_blksum[SCAN_NB];
__device__ int      g_is32;
__device__ float    g_agg[(size_t)NN * 512];
// pre-split weights, bf16 hi/lo: [0]=s_root [1]=s_rel [2]=v_root [3]=v_rel
__device__ uint16_t g_whi[4][16384];
__device__ uint16_t g_wlo[4][16384];

// ================= warp-mma helpers (sm_80+ PTX, valid for compute_103) =========
__device__ __forceinline__ uint32_t smem_u32(const void* p) {
    uint32_t a;
    asm("{ .reg .u64 t; cvta.to.shared.u64 t, %1; cvt.u32.u64 %0, t; }" : "=r"(a) : "l"(p));
    return a;
}
__device__ __forceinline__ void ldsm_x4(uint32_t* r, uint32_t addr) {
    asm volatile("ldmatrix.sync.aligned.m8n8.x4.shared.b16 {%0,%1,%2,%3}, [%4];"
                 : "=r"(r[0]), "=r"(r[1]), "=r"(r[2]), "=r"(r[3]) : "r"(addr));
}
__device__ __forceinline__ void ldsm_x2(uint32_t* r, uint32_t addr) {
    asm volatile("ldmatrix.sync.aligned.m8n8.x2.shared.b16 {%0,%1}, [%2];"
                 : "=r"(r[0]), "=r"(r[1]) : "r"(addr));
}
__device__ __forceinline__ void mma_bf16(float* c, const uint32_t* a, const uint32_t* b) {
    asm volatile("mma.sync.aligned.m16n8k16.row.col.f32.bf16.bf16.f32 "
                 "{%0,%1,%2,%3}, {%4,%5,%6,%7}, {%8,%9}, {%0,%1,%2,%3};"
                 : "+f"(c[0]), "+f"(c[1]), "+f"(c[2]), "+f"(c[3])
                 : "r"(a[0]), "r"(a[1]), "r"(a[2]), "r"(a[3]), "r"(b[0]), "r"(b[1]));
}
__device__ __forceinline__ uint32_t pack_bf16x2(float hi_el, float lo_el) {
    uint32_t r;
    asm("cvt.rn.bf16x2.f32 %0, %1, %2;" : "=r"(r) : "f"(hi_el), "f"(lo_el));
    return r;
}

// ---------------- dtype detection + zero (fused) ----------------
__global__ void k_init() {
    int i = blockIdx.x * blockDim.x + threadIdx.x;
    if (i == 0) g_is32 = 0;
    if (i < NN) g_cnt[i] = 0;
}

__global__ void k_dtype_detect(const long long* __restrict__ ei) {
    int e = blockIdx.x * blockDim.x + threadIdx.x;
    if (e < EE) {
        long long v = ei[e];
        if (v < 0 || v >= NN) atomicOr(&g_is32, 1);
    }
}

__device__ __forceinline__ int load_idx(const void* ei, int pos, int is32) {
    long long v;
    if (is32) v = ((const int*)ei)[pos];
    else      v = ((const long long*)ei)[pos];
    int r = (int)v;
    if (r < 0) r = 0;
    if (r >= NN) r = NN - 1;
    return r;
}

// ---------------- weight pre-split: fp32 -> bf16 hi + bf16 lo ----------------
__global__ void __launch_bounds__(256) k_wsplit(const float* __restrict__ a,
                                                const float* __restrict__ b,
                                                const float* __restrict__ c,
                                                const float* __restrict__ d) {
    int i = blockIdx.x * 256 + threadIdx.x;      // 0..65535
    int mat = i >> 14;
    int idx = i & 16383;
    const float* src = (mat == 0) ? a : (mat == 1) ? b : (mat == 2) ? c : d;
    float f = src[idx];
    uint32_t u = __float_as_uint(f);
    g_whi[mat][idx] = (uint16_t)(u >> 16);                       // truncation (same as round-10 inline)
    float lo = f - __uint_as_float(u & 0xFFFF0000u);             // exact residual
    g_wlo[mat][idx] = (uint16_t)(pack_bf16x2(0.f, lo) & 0xFFFFu);
}

// ---------------- CSR build ----------------
__global__ void k_hist(const void* __restrict__ ei) {
    int e = blockIdx.x * blockDim.x + threadIdx.x;
    if (e < EE) {
        int is32 = g_is32;
        int r = load_idx(ei, e, is32);
        atomicAdd(&g_cnt[r], 1);
    }
}

__global__ void __launch_bounds__(256) k_scan1() {
    __shared__ int s[256];
    int t = threadIdx.x;
    int i = blockIdx.x * 256 + t;
    int v = (i < NN) ? g_cnt[i] : 0;
    s[t] = v;
    __syncthreads();
#pragma unroll
    for (int d = 1; d < 256; d <<= 1) {
        int u = (t >= d) ? s[t - d] : 0;
        __syncthreads();
        s[t] += u;
        __syncthreads();
    }
    if (i < NN) g_off[i] = s[t] - v;
    if (t == 255) g_blksum[blockIdx.x] = s[255];
}

__global__ void __launch_bounds__(256) k_scan2() {
    __shared__ int s[256];
    int t = threadIdx.x;
    int v = (t < SCAN_NB) ? g_blksum[t] : 0;
    s[t] = v;
    __syncthreads();
#pragma unroll
    for (int d = 1; d < 256; d <<= 1) {
        int u = (t >= d) ? s[t - d] : 0;
        __syncthreads();
        s[t] += u;
        __syncthreads();
    }
    if (t < SCAN_NB) g_blksum[t] = s[t] - v;
}

__global__ void __launch_bounds__(256) k_scan3() {
    int t = threadIdx.x;
    int i = blockIdx.x * 256 + t;
    if (i < NN) {
        int o = g_off[i] + g_blksum[blockIdx.x];
        g_off[i] = o;
        g_cur[i] = o;
    }
    if (i == NN) g_off[NN] = EE;
}

__global__ void k_fill(const void* __restrict__ ei) {
    int e = blockIdx.x * blockDim.x + threadIdx.x;
    if (e < EE) {
        int is32 = g_is32;
        int r = load_idx(ei, e, is32);
        int c = load_idx(ei, EE + e, is32);
        int p = atomicAdd(&g_cur[r], 1);
        g_cols[p] = c;
    }
}

// ---------------- aggregate raw features: agg[n] = sum_{e: row=n} x[col_e] ----------------
__global__ void __launch_bounds__(128) k_agg(const float4* __restrict__ xv) {
    int n = blockIdx.x;
    int t = threadIdx.x;
    int beg = g_off[n], end = g_off[n + 1];
    float4 acc = make_float4(0.f, 0.f, 0.f, 0.f);
    int j = beg;
    for (; j + 3 < end; j += 4) {
        int c0 = g_cols[j], c1 = g_cols[j + 1], c2 = g_cols[j + 2], c3 = g_cols[j + 3];
        float4 v0 = xv[(size_t)c0 * 128 + t];
        float4 v1 = xv[(size_t)c1 * 128 + t];
        float4 v2 = xv[(size_t)c2 * 128 + t];
        float4 v3 = xv[(size_t)c3 * 128 + t];
        acc.x += v0.x + v1.x + v2.x + v3.x;
        acc.y += v0.y + v1.y + v2.y + v3.y;
        acc.z += v0.z + v1.z + v2.z + v3.z;
        acc.w += v0.w + v1.w + v2.w + v3.w;
    }
    for (; j < end; j++) {
        int c0 = g_cols[j];
        float4 v0 = xv[(size_t)c0 * 128 + t];
        acc.x += v0.x; acc.y += v0.y; acc.z += v0.z; acc.w += v0.w;
    }
    ((float4*)g_agg)[(size_t)n * 128 + t] = acc;
}

// ---------------- fused 3xBF16 mma.sync GEMM (round-10 structure + presplit B) --------
// block < NB0: scalar rows (mode 0, +bias). block >= NB0: vector rows (mode 1).
// 128x128 tile, K=256 in 8 chunks of 32. Single-buffered 41KB static smem
// (2 blocks/SM), 2 syncs per chunk — the proven round-10 pipeline.
// A: fp32 LDG -> reg split -> bf16 hi/lo STS.  B: pre-split bf16 LDG -> STS.

#define TSTRIDE 80                      // bytes per 32-bf16 row (64 + 16 pad)
#define SM_ROFF 0                       // int[128]
#define SM_AHI  512
#define SM_ALO  (512 + 10240)
#define SM_BHI  (512 + 20480)
#define SM_BLO  (512 + 30720)
#define SM_TOT  (512 + 40960)

__global__ void __launch_bounds__(256) k_mgemm(const float* __restrict__ X,
                                               const float* __restrict__ bias,
                                               float* __restrict__ out) {
    __shared__ __align__(16) char sm[SM_TOT];
    int* roff_s = (int*)(sm + SM_ROFF);
    uint32_t sbase = smem_u32(sm);

    int tid = threadIdx.x;
    int lane = tid & 31;
    int wid = tid >> 5;

    int mode, mb, Mloc;
    if (blockIdx.x < NB0) { mode = 0; mb = (int)blockIdx.x;       Mloc = NN; }
    else                  { mode = 1; mb = (int)blockIdx.x - NB0; Mloc = 3 * NN; }
    int mbase = mb * 128;

    if (tid < 128) {
        int m = mbase + tid;
        if (m >= Mloc) m = Mloc - 1;     // clamp: duplicate loads, stores guarded
        int off;
        if (mode == 0) off = m * 512;
        else { int n = m / 3; int ch = 1 + (m % 3); off = n * 512 + ch * 128; }
        roff_s[tid] = off;
    }
    __syncthreads();

    // --- load roles ---
    int lrow = tid >> 1;                 // 0..127
    int khf  = (tid & 1) * 16;           // element offset within 32-wide chunk
    int arow = roff_s[lrow];
    uint32_t st_off = (uint32_t)lrow * TSTRIDE + (uint32_t)khf * 2;  // bytes

    const uint16_t* WH0 = g_whi[mode * 2 + 0];  // root
    const uint16_t* WH1 = g_whi[mode * 2 + 1];  // rel
    const uint16_t* WL0 = g_wlo[mode * 2 + 0];
    const uint16_t* WL1 = g_wlo[mode * 2 + 1];

    // --- compute roles ---
    int warpM = wid & 3;
    int warpN = wid >> 2;
    int g  = lane >> 3;
    int rr = lane & 7;
    uint32_t aoff0 = (uint32_t)(warpM * 32 + 0  + rr + (g & 1) * 8) * TSTRIDE + (g >> 1) * 16;
    uint32_t aoff1 = (uint32_t)(warpM * 32 + 16 + rr + (g & 1) * 8) * TSTRIDE + (g >> 1) * 16;
    uint32_t boff  = (uint32_t)(warpN * 64 + rr) * TSTRIDE + ((lane >> 3) & 1) * 16;

    float acc[2][8][4];
#pragma unroll
    for (int mt = 0; mt < 2; mt++)
#pragma unroll
        for (int nt = 0; nt < 8; nt++)
#pragma unroll
            for (int q = 0; q < 4; q++) acc[mt][nt][q] = 0.f;

    const float* Agg = g_agg;

#pragma unroll 1
    for (int c = 0; c < 8; c++) {
        bool fh = (c < 4);
        int koff = (c & 3) * 32;
        const float* pa = (fh ? X : Agg) + arow + koff + khf;
        const uint16_t* pbh = (fh ? WH0 : WH1) + lrow * 128 + koff + khf;
        const uint16_t* pbl = (fh ? WL0 : WL1) + lrow * 128 + koff + khf;

        // A: load 16 floats, split to bf16 hi/lo in registers
        uint2 ahi[4], alo[4];
#pragma unroll
        for (int q = 0; q < 4; q++) {
            float4 f = ((const float4*)pa)[q];
            uint32_t ux = __float_as_uint(f.x), uy = __float_as_uint(f.y);
            uint32_t uz = __float_as_uint(f.z), uw = __float_as_uint(f.w);
            ahi[q].x = __byte_perm(ux, uy, 0x7632);
            ahi[q].y = __byte_perm(uz, uw, 0x7632);
            float lx = f.x - __uint_as_float(ux & 0xFFFF0000u);
            float ly = f.y - __uint_as_float(uy & 0xFFFF0000u);
            float lz = f.z - __uint_as_float(uz & 0xFFFF0000u);
            float lw = f.w - __uint_as_float(uw & 0xFFFF0000u);
            alo[q].x = pack_bf16x2(ly, lx);
            alo[q].y = pack_bf16x2(lw, lz);
        }
        // B: pre-split bf16, straight loads
        uint4 bh0 = ((const uint4*)pbh)[0], bh1 = ((const uint4*)pbh)[1];
        uint4 bl0 = ((const uint4*)pbl)[0], bl1 = ((const uint4*)pbl)[1];

        __syncthreads();   // previous chunk's compute done reading tiles
#pragma unroll
        for (int q = 0; q < 4; q++) {
            *(uint2*)(sm + SM_AHI + st_off + q * 8) = ahi[q];
            *(uint2*)(sm + SM_ALO + st_off + q * 8) = alo[q];
        }
        *(uint4*)(sm + SM_BHI + st_off)      = bh0;
        *(uint4*)(sm + SM_BHI + st_off + 16) = bh1;
        *(uint4*)(sm + SM_BLO + st_off)      = bl0;
        *(uint4*)(sm + SM_BLO + st_off + 16) = bl1;
        __syncthreads();

        // compute: 2 k16 steps
#pragma unroll
        for (int ks = 0; ks < 2; ks++) {
            uint32_t a0h[4], a0l[4], a1h[4], a1l[4];
            ldsm_x4(a0h, sbase + SM_AHI + aoff0 + ks * 32);
            ldsm_x4(a0l, sbase + SM_ALO + aoff0 + ks * 32);
            ldsm_x4(a1h, sbase + SM_AHI + aoff1 + ks * 32);
            ldsm_x4(a1l, sbase + SM_ALO + aoff1 + ks * 32);
#pragma unroll
            for (int nt = 0; nt < 8; nt++) {
                uint32_t bh[2], bl[2];
                ldsm_x2(bh, sbase + SM_BHI + boff + nt * (8 * TSTRIDE) + ks * 32);
                ldsm_x2(bl, sbase + SM_BLO + boff + nt * (8 * TSTRIDE) + ks * 32);
                mma_bf16(acc[0][nt], a0h, bh);
                mma_bf16(acc[0][nt], a0l, bh);
                mma_bf16(acc[0][nt], a0h, bl);
                mma_bf16(acc[1][nt], a1h, bh);
                mma_bf16(acc[1][nt], a1l, bh);
                mma_bf16(acc[1][nt], a1h, bl);
            }
        }
    }

    // epilogue
#pragma unroll
    for (int mt = 0; mt < 2; mt++) {
        int lr0 = warpM * 32 + mt * 16 + (lane >> 2);
        int lr1 = lr0 + 8;
        bool live0 = (mbase + lr0) < Mloc;
        bool live1 = (mbase + lr1) < Mloc;
        int o0 = roff_s[lr0];
        int o1 = roff_s[lr1];
#pragma unroll
        for (int nt = 0; nt < 8; nt++) {
            int col = warpN * 64 + nt * 8 + 2 * (lane & 3);
            float b0 = 0.f, b1 = 0.f;
            if (mode == 0) { b0 = bias[col]; b1 = bias[col + 1]; }
            if (live0) {
                float2 v = make_float2(acc[mt][nt][0] + b0, acc[mt][nt][1] + b1);
                *(float2*)(out + o0 + col) = v;
            }
            if (live1) {
                float2 v = make_float2(acc[mt][nt][2] + b0, acc[mt][nt][3] + b1);
                *(float2*)(out + o1 + col) = v;
            }
        }
    }
}

extern "C" void kernel_launch(void* const* d_in, const int* in_sizes, int n_in,
                              void* d_out, int out_size) {
    const float* x        = (const float*)d_in[0];
    const void*  ei       = d_in[1];
    const float* W_s_rel  = (const float*)d_in[2];
    const float* W_s_root = (const float*)d_in[3];
    const float* b_s_root = (const float*)d_in[4];
    const float* W_v_rel  = (const float*)d_in[5];
    const float* W_v_root = (const float*)d_in[6];
    float*       out      = (float*)d_out;

    k_init<<<(NN + 255) / 256, 256>>>();
    k_dtype_detect<<<(EE + 255) / 256, 256>>>((const long long*)ei);
    k_wsplit<<<256, 256>>>(W_s_root, W_s_rel, W_v_root, W_v_rel);
    k_hist<<<(EE + 255) / 256, 256>>>(ei);
    k_scan1<<<SCAN_NB, 256>>>();
    k_scan2<<<1, 256>>>();
    k_scan3<<<SCAN_NB + 1, 256>>>();
    k_fill<<<(EE + 255) / 256, 256>>>(ei);
    k_agg<<<NN, 128>>>((const float4*)x);

    k_mgemm<<<NB0 + NB1, 256>>>(x, b_s_root, out);
}